// round 2
// baseline (speedup 1.0000x reference)
#include <cuda_runtime.h>
#include <math.h>

#define OBSD 194
#define HD   64
#define AD   5
#define ED   3
#define BLOCK 128

// chunking of the [194,64] weight matrices: rows 0..97 then 98..193
#define CH0_ROWS 98
#define CH1_ROWS 96
#define CH0_F2   49   /* float2 x-elements covering rows 0..97  */
#define CH1_F2   48   /* float2 x-elements covering rows 98..193 */

__global__ void __launch_bounds__(BLOCK)
agent_ac_kernel(const float* __restrict__ x,   const int*   __restrict__ action,
                const float* __restrict__ W1,  const float* __restrict__ b1,
                const float* __restrict__ W2,  const float* __restrict__ b2,
                const float* __restrict__ Wh,  const float* __restrict__ bh,
                const float* __restrict__ Wc1, const float* __restrict__ bc1,
                const float* __restrict__ Wc2, const float* __restrict__ bc2,
                const float* __restrict__ Wc3, const float* __restrict__ bc3,
                float* __restrict__ out, int Bn)
{
    __shared__ float ws[CH0_ROWS * HD];   // 98*64*4 = 25088 B (reused for all layers)
    __shared__ float bs[HD];
    __shared__ float whs[ED * HD * AD];   // 960 floats
    __shared__ float bhs[16];
    __shared__ float wc3s[HD];

    const int tid = threadIdx.x;
    const int s   = blockIdx.x * BLOCK + tid;
    const int sr  = (s < Bn) ? s : (Bn - 1);

    // small persistent weights — loaded once, covered by the first __syncthreads
    for (int i = tid; i < ED*HD*AD; i += BLOCK) whs[i]  = Wh[i];
    for (int i = tid; i < ED*AD;    i += BLOCK) bhs[i]  = bh[i];
    for (int i = tid; i < HD;       i += BLOCK) wc3s[i] = Wc3[i];

    const float2* xr = (const float2*)(x + (size_t)sr * OBSD);  // rows are 8B-aligned (776 B)

    float h[HD], f[HD];

    // event routing needs x[0..2]
    float x0, x1v, x2v;
    {
        float2 v0 = __ldg(&xr[0]);
        float2 v1 = __ldg(&xr[1]);
        x0 = v0.x; x1v = v0.y; x2v = v1.x;
    }

    // ===================== actor layer 1: h = tanh(x@W1 + b1) =====================
    for (int i = tid; i < CH0_ROWS*HD; i += BLOCK) ws[i] = W1[i];
    for (int i = tid; i < HD;          i += BLOCK) bs[i] = b1[i];
    __syncthreads();

    #pragma unroll
    for (int j = 0; j < HD; j++) h[j] = bs[j];
    for (int kk = 0; kk < CH0_F2; kk++) {
        const float2 xv = __ldg(&xr[kk]);
        const float* wa = &ws[(2*kk  ) * HD];
        const float* wb = &ws[(2*kk+1) * HD];
        #pragma unroll
        for (int j = 0; j < HD; j++) h[j] = fmaf(xv.x, wa[j], h[j]);
        #pragma unroll
        for (int j = 0; j < HD; j++) h[j] = fmaf(xv.y, wb[j], h[j]);
    }
    __syncthreads();
    for (int i = tid; i < CH1_ROWS*HD; i += BLOCK) ws[i] = W1[CH0_ROWS*HD + i];
    __syncthreads();
    for (int kk = CH0_F2; kk < CH0_F2 + CH1_F2; kk++) {
        const float2 xv = __ldg(&xr[kk]);
        const float* wa = &ws[(2*kk   - CH0_ROWS) * HD];
        const float* wb = &ws[(2*kk+1 - CH0_ROWS) * HD];
        #pragma unroll
        for (int j = 0; j < HD; j++) h[j] = fmaf(xv.x, wa[j], h[j]);
        #pragma unroll
        for (int j = 0; j < HD; j++) h[j] = fmaf(xv.y, wb[j], h[j]);
    }
    #pragma unroll
    for (int j = 0; j < HD; j++) h[j] = tanhf(h[j]);

    // ===================== actor layer 2: f = tanh(h@W2 + b2) =====================
    __syncthreads();
    for (int i = tid; i < HD*HD; i += BLOCK) ws[i] = W2[i];
    for (int i = tid; i < HD;    i += BLOCK) bs[i] = b2[i];
    __syncthreads();

    #pragma unroll
    for (int j = 0; j < HD; j++) f[j] = bs[j];
    #pragma unroll
    for (int k = 0; k < HD; k++) {
        const float hk = h[k];
        const float* wr = &ws[k*HD];
        #pragma unroll
        for (int j = 0; j < HD; j++) f[j] = fmaf(hk, wr[j], f[j]);
    }
    #pragma unroll
    for (int j = 0; j < HD; j++) f[j] = tanhf(f[j]);

    // ===================== head: event routing + log-softmax =====================
    int ev = 0; float bx = x0;
    if (x1v > bx) { bx = x1v; ev = 1; }
    if (x2v > bx) { ev = 2; }

    float lg[AD];
    #pragma unroll
    for (int a = 0; a < AD; a++) lg[a] = bhs[ev*AD + a];
    const float* whe = &whs[ev*HD*AD];
    #pragma unroll
    for (int k = 0; k < HD; k++) {
        const float fk = f[k];
        #pragma unroll
        for (int a = 0; a < AD; a++) lg[a] = fmaf(fk, whe[k*AD + a], lg[a]);
    }

    float m = lg[0];
    #pragma unroll
    for (int a = 1; a < AD; a++) m = fmaxf(m, lg[a]);
    float se = 0.f;
    #pragma unroll
    for (int a = 0; a < AD; a++) se += expf(lg[a] - m);
    const float lse = logf(se);
    float ent = 0.f;
    #pragma unroll
    for (int a = 0; a < AD; a++) {
        const float lp = lg[a] - m - lse;
        ent -= expf(lp) * lp;
    }
    const int   act  = action[sr];
    const float logp = lg[act] - m - lse;

    // ===================== critic layer 1: h = tanh(x@Wc1 + bc1) =====================
    __syncthreads();
    for (int i = tid; i < CH0_ROWS*HD; i += BLOCK) ws[i] = Wc1[i];
    for (int i = tid; i < HD;          i += BLOCK) bs[i] = bc1[i];
    __syncthreads();

    #pragma unroll
    for (int j = 0; j < HD; j++) h[j] = bs[j];
    for (int kk = 0; kk < CH0_F2; kk++) {
        const float2 xv = __ldg(&xr[kk]);   // L2 hit on second pass (x slice ~97KB/block)
        const float* wa = &ws[(2*kk  ) * HD];
        const float* wb = &ws[(2*kk+1) * HD];
        #pragma unroll
        for (int j = 0; j < HD; j++) h[j] = fmaf(xv.x, wa[j], h[j]);
        #pragma unroll
        for (int j = 0; j < HD; j++) h[j] = fmaf(xv.y, wb[j], h[j]);
    }
    __syncthreads();
    for (int i = tid; i < CH1_ROWS*HD; i += BLOCK) ws[i] = Wc1[CH0_ROWS*HD + i];
    __syncthreads();
    for (int kk = CH0_F2; kk < CH0_F2 + CH1_F2; kk++) {
        const float2 xv = __ldg(&xr[kk]);
        const float* wa = &ws[(2*kk   - CH0_ROWS) * HD];
        const float* wb = &ws[(2*kk+1 - CH0_ROWS) * HD];
        #pragma unroll
        for (int j = 0; j < HD; j++) h[j] = fmaf(xv.x, wa[j], h[j]);
        #pragma unroll
        for (int j = 0; j < HD; j++) h[j] = fmaf(xv.y, wb[j], h[j]);
    }
    #pragma unroll
    for (int j = 0; j < HD; j++) h[j] = tanhf(h[j]);

    // ===================== critic layer 2 + value =====================
    __syncthreads();
    for (int i = tid; i < HD*HD; i += BLOCK) ws[i] = Wc2[i];
    for (int i = tid; i < HD;    i += BLOCK) bs[i] = bc2[i];
    __syncthreads();

    #pragma unroll
    for (int j = 0; j < HD; j++) f[j] = bs[j];
    #pragma unroll
    for (int k = 0; k < HD; k++) {
        const float hk = h[k];
        const float* wr = &ws[k*HD];
        #pragma unroll
        for (int j = 0; j < HD; j++) f[j] = fmaf(hk, wr[j], f[j]);
    }
    float val = __ldg(&bc3[0]);
    #pragma unroll
    for (int j = 0; j < HD; j++) val = fmaf(tanhf(f[j]), wc3s[j], val);

    // ===================== outputs: [action | logp | entropy | value] =====================
    if (s < Bn) {
        out[s]        = (float)act;
        out[Bn   + s] = logp;
        out[2*Bn + s] = ent;
        out[3*Bn + s] = val;
    }
}

extern "C" void kernel_launch(void* const* d_in, const int* in_sizes, int n_in,
                              void* d_out, int out_size) {
    const float* x    = (const float*)d_in[0];
    const int*   act  = (const int*)  d_in[1];
    const float* W1   = (const float*)d_in[2];
    const float* b1   = (const float*)d_in[3];
    const float* W2   = (const float*)d_in[4];
    const float* b2   = (const float*)d_in[5];
    const float* Wh   = (const float*)d_in[6];
    const float* bh   = (const float*)d_in[7];
    const float* Wc1  = (const float*)d_in[8];
    const float* bc1  = (const float*)d_in[9];
    const float* Wc2  = (const float*)d_in[10];
    const float* bc2  = (const float*)d_in[11];
    const float* Wc3  = (const float*)d_in[12];
    const float* bc3  = (const float*)d_in[13];
    float* out = (float*)d_out;

    const int Bn   = in_sizes[1];   // action element count = batch
    const int grid = (Bn + BLOCK - 1) / BLOCK;

    agent_ac_kernel<<<grid, BLOCK>>>(
        x, act, W1, b1, W2, b2, Wh, bh, Wc1, bc1, Wc2, bc2, Wc3, bc3, out, Bn);
}

// round 4
// speedup vs baseline: 2.1660x; 2.1660x over previous
#include <cuda_runtime.h>
#include <math.h>
#include <stdint.h>

#define OBSD 194
#define HD   64
#define AD   5
#define ED   3
#define BLOCK 256
#define ROWS  128        // samples per CTA
#define NCH1  7          // K chunks of 32 covering 194 (padded to 224)
#define STR   36         // smem stride for mma staging (conflict-free frags)

__device__ __forceinline__ float tf32r(float f) {
    uint32_t r; asm("cvt.rna.tf32.f32 %0, %1;" : "=r"(r) : "f"(f));
    return __uint_as_float(r);
}
__device__ __forceinline__ float tanha(float x) {
    float y; asm("tanh.approx.f32 %0, %1;" : "=f"(y) : "f"(x)); return y;
}
__device__ __forceinline__ void mma8(float* c, uint32_t a0, uint32_t a1, uint32_t a2,
                                     uint32_t a3, uint32_t b0, uint32_t b1) {
    asm volatile("mma.sync.aligned.m16n8k8.row.col.f32.tf32.tf32.f32 "
                 "{%0,%1,%2,%3},{%4,%5,%6,%7},{%8,%9},{%0,%1,%2,%3};"
                 : "+f"(c[0]), "+f"(c[1]), "+f"(c[2]), "+f"(c[3])
                 : "r"(a0), "r"(a1), "r"(a2), "r"(a3), "r"(b0), "r"(b1));
}
#define F2U(x) __float_as_uint(x)

__global__ void __launch_bounds__(BLOCK)
agent_mma(const float* __restrict__ x,   const int* __restrict__ action,
          const float* __restrict__ W1,  const float* __restrict__ b1,
          const float* __restrict__ W2,  const float* __restrict__ b2,
          const float* __restrict__ Wh,  const float* __restrict__ bh,
          const float* __restrict__ Wc1, const float* __restrict__ bc1,
          const float* __restrict__ Wc2, const float* __restrict__ bc2,
          const float* __restrict__ Wc3, const float* __restrict__ bc3,
          float* __restrict__ out, int Bn)
{
    __shared__ float spool[9216];          // xs = spool[0..4607], bbuf = spool[4608..9215]
    __shared__ float whs[ED * HD * AD];    // Wh [E][H][A]
    __shared__ float bhs[16];
    __shared__ float b1s[HD], b2s[HD], bc1s[HD], bc2s[HD], wc3s[HD];
    __shared__ float valbuf[ROWS];

    float* xs   = spool;
    float* bbuf = spool + 4608;

    const int tid  = threadIdx.x;
    const int lane = tid & 31;
    const int warp = tid >> 5;
    const int g    = lane >> 2;     // 0..7
    const int tg   = lane & 3;      // 0..3
    const int rb   = warp * 16;     // row base of this warp's m16 tile
    const int s0   = blockIdx.x * ROWS;

    // small weights/biases
    for (int i = tid; i < ED * HD * AD; i += BLOCK) whs[i] = Wh[i];
    if (tid < ED * AD) bhs[tid] = bh[tid];
    if (tid < HD) {
        b1s[tid] = b1[tid];  b2s[tid] = b2[tid];
        bc1s[tid] = bc1[tid]; bc2s[tid] = bc2[tid]; wc3s[tid] = Wc3[tid];
    }
    const float bc3v = __ldg(&bc3[0]);

    // ======================= GEMM1: C1[128x128] = X @ [W1|Wc1] =======================
    float acc[16][4];
    #pragma unroll
    for (int nt = 0; nt < 16; nt++)
        #pragma unroll
        for (int i = 0; i < 4; i++) acc[nt][i] = 0.f;

    for (int c = 0; c < NCH1; c++) {
        __syncthreads();   // staging buffers free (also covers smalls on first iter)
        // stage X chunk [128 rows x 32 k], tf32-rounded
        #pragma unroll
        for (int it = 0; it < 16; it++) {
            int e = tid + it * BLOCK;           // 0..4095
            int row = e >> 5, k = e & 31;
            int col = 32 * c + k;
            int srow = s0 + row; if (srow >= Bn) srow = Bn - 1;
            float v = (col < OBSD) ? __ldg(&x[(size_t)srow * OBSD + col]) : 0.f;
            xs[row * STR + k] = tf32r(v);
        }
        // stage B chunk [n=128][k=32]: bbuf[n][k] = Wcol n at row kg
        #pragma unroll
        for (int it = 0; it < 16; it++) {
            int e = tid + it * BLOCK;
            int k = e >> 7, n = e & 127;
            int kg = 32 * c + k;
            float v = 0.f;
            if (kg < OBSD) v = (n < HD) ? __ldg(&W1[kg * HD + n])
                                        : __ldg(&Wc1[kg * HD + (n - HD)]);
            bbuf[n * STR + k] = tf32r(v);
        }
        __syncthreads();
        #pragma unroll
        for (int k8 = 0; k8 < 4; k8++) {
            const int kk = k8 * 8 + tg;
            uint32_t a0 = F2U(xs[(rb + g)     * STR + kk]);
            uint32_t a1 = F2U(xs[(rb + g + 8) * STR + kk]);
            uint32_t a2 = F2U(xs[(rb + g)     * STR + kk + 4]);
            uint32_t a3 = F2U(xs[(rb + g + 8) * STR + kk + 4]);
            #pragma unroll
            for (int nt = 0; nt < 16; nt++) {
                uint32_t b0 = F2U(bbuf[(8 * nt + g) * STR + kk]);
                uint32_t b1v = F2U(bbuf[(8 * nt + g) * STR + kk + 4]);
                mma8(acc[nt], a0, a1, a2, a3, b0, b1v);
            }
        }
    }
    __syncthreads();

    // epilogue1: bias + tanh in fragment registers (actor nt 0..7, critic nt 8..15)
    #pragma unroll
    for (int nt = 0; nt < 16; nt++) {
        int n0 = 8 * nt + 2 * tg;               // 0..127
        float ba0 = (nt < 8) ? b1s[n0]     : bc1s[n0 - HD];
        float ba1 = (nt < 8) ? b1s[n0 + 1] : bc1s[n0 + 1 - HD];
        acc[nt][0] = tanha(acc[nt][0] + ba0);
        acc[nt][1] = tanha(acc[nt][1] + ba1);
        acc[nt][2] = tanha(acc[nt][2] + ba0);
        acc[nt][3] = tanha(acc[nt][3] + ba1);
    }

    // ======================= GEMM2 (x2): H[128x64] @ W[64x64] =======================
    float feat[8][4];     // actor output fragments
    float acc2[8][4];

    #pragma unroll
    for (int pass = 0; pass < 2; pass++) {
        const int base = pass * 8;                       // acc half: actor then critic
        const float* Wm = pass ? Wc2 : W2;
        #pragma unroll
        for (int nt = 0; nt < 8; nt++)
            #pragma unroll
            for (int i = 0; i < 4; i++) acc2[nt][i] = 0.f;

        for (int kh = 0; kh < 2; kh++) {
            // stage H chunk from registers (k = hidden dim 32*kh..32*kh+31)
            #pragma unroll
            for (int q = 0; q < 4; q++) {
                int ntl = 4 * kh + q;                    // layer1 n-tile within half
                int nh = 8 * ntl + 2 * tg;               // hidden index
                int kc = nh - 32 * kh;                   // 0..31
                xs[(rb + g)     * STR + kc]     = tf32r(acc[base + ntl][0]);
                xs[(rb + g)     * STR + kc + 1] = tf32r(acc[base + ntl][1]);
                xs[(rb + g + 8) * STR + kc]     = tf32r(acc[base + ntl][2]);
                xs[(rb + g + 8) * STR + kc + 1] = tf32r(acc[base + ntl][3]);
            }
            // stage W chunk [n=64][k=32]
            #pragma unroll
            for (int it = 0; it < 8; it++) {
                int e = tid + it * BLOCK;                // 0..2047
                int k = e >> 6, n = e & 63;
                int kg = 32 * kh + k;
                bbuf[n * STR + k] = tf32r(__ldg(&Wm[kg * HD + n]));
            }
            __syncthreads();
            #pragma unroll
            for (int k8 = 0; k8 < 4; k8++) {
                const int kk = k8 * 8 + tg;
                uint32_t a0 = F2U(xs[(rb + g)     * STR + kk]);
                uint32_t a1 = F2U(xs[(rb + g + 8) * STR + kk]);
                uint32_t a2 = F2U(xs[(rb + g)     * STR + kk + 4]);
                uint32_t a3 = F2U(xs[(rb + g + 8) * STR + kk + 4]);
                #pragma unroll
                for (int nt = 0; nt < 8; nt++) {
                    uint32_t b0 = F2U(bbuf[(8 * nt + g) * STR + kk]);
                    uint32_t b1v = F2U(bbuf[(8 * nt + g) * STR + kk + 4]);
                    mma8(acc2[nt], a0, a1, a2, a3, b0, b1v);
                }
            }
            __syncthreads();
        }

        if (pass == 0) {
            // actor: feat = tanh(acc2 + b2)
            #pragma unroll
            for (int nt = 0; nt < 8; nt++) {
                int n0 = 8 * nt + 2 * tg;
                feat[nt][0] = tanha(acc2[nt][0] + b2s[n0]);
                feat[nt][1] = tanha(acc2[nt][1] + b2s[n0 + 1]);
                feat[nt][2] = tanha(acc2[nt][2] + b2s[n0]);
                feat[nt][3] = tanha(acc2[nt][3] + b2s[n0 + 1]);
            }
        } else {
            // critic: val = tanh(acc2 + bc2) . Wc3, reduced across the quad (tg lanes)
            float v0 = 0.f, v1 = 0.f;
            #pragma unroll
            for (int nt = 0; nt < 8; nt++) {
                int n0 = 8 * nt + 2 * tg;
                v0 = fmaf(tanha(acc2[nt][0] + bc2s[n0]),     wc3s[n0],     v0);
                v0 = fmaf(tanha(acc2[nt][1] + bc2s[n0 + 1]), wc3s[n0 + 1], v0);
                v1 = fmaf(tanha(acc2[nt][2] + bc2s[n0]),     wc3s[n0],     v1);
                v1 = fmaf(tanha(acc2[nt][3] + bc2s[n0 + 1]), wc3s[n0 + 1], v1);
            }
            v0 += __shfl_xor_sync(0xFFFFFFFF, v0, 1);
            v0 += __shfl_xor_sync(0xFFFFFFFF, v0, 2);
            v1 += __shfl_xor_sync(0xFFFFFFFF, v1, 1);
            v1 += __shfl_xor_sync(0xFFFFFFFF, v1, 2);
            if (tg == 0) {
                valbuf[rb + g]     = v0 + bc3v;
                valbuf[rb + g + 8] = v1 + bc3v;
            }
        }
    }

    // ======================= feat -> smem pool (stride 65) =======================
    float* fbuf = spool;    // reuse: 128 x 65 = 8320 floats <= 9216
    #pragma unroll
    for (int nt = 0; nt < 8; nt++) {
        int n0 = 8 * nt + 2 * tg;
        fbuf[(rb + g)     * 65 + n0]     = feat[nt][0];
        fbuf[(rb + g)     * 65 + n0 + 1] = feat[nt][1];
        fbuf[(rb + g + 8) * 65 + n0]     = feat[nt][2];
        fbuf[(rb + g + 8) * 65 + n0 + 1] = feat[nt][3];
    }
    __syncthreads();

    // ======================= per-sample head (threads 0..127) =======================
    if (tid < ROWS) {
        int s = s0 + tid;
        int sr = (s < Bn) ? s : (Bn - 1);
        const float* xrow = x + (size_t)sr * OBSD;
        float x0 = __ldg(&xrow[0]), x1v = __ldg(&xrow[1]), x2v = __ldg(&xrow[2]);
        int ev = 0; float bx = x0;
        if (x1v > bx) { bx = x1v; ev = 1; }
        if (x2v > bx) { ev = 2; }

        float lg[AD];
        #pragma unroll
        for (int a = 0; a < AD; a++) lg[a] = bhs[ev * AD + a];
        const float* fr  = &fbuf[tid * 65];
        const float* whe = &whs[ev * HD * AD];
        #pragma unroll 8
        for (int k = 0; k < HD; k++) {
            float fk = fr[k];
            #pragma unroll
            for (int a = 0; a < AD; a++) lg[a] = fmaf(fk, whe[k * AD + a], lg[a]);
        }
        float m = lg[0];
        #pragma unroll
        for (int a = 1; a < AD; a++) m = fmaxf(m, lg[a]);
        float se = 0.f;
        #pragma unroll
        for (int a = 0; a < AD; a++) se += expf(lg[a] - m);
        float lse = logf(se);
        float ent = 0.f;
        #pragma unroll
        for (int a = 0; a < AD; a++) {
            float lp = lg[a] - m - lse;
            ent -= expf(lp) * lp;
        }
        int   act  = __ldg(&action[sr]);
        float logp = lg[act] - m - lse;

        if (s < Bn) {
            out[s]          = (float)act;
            out[Bn + s]     = logp;
            out[2 * Bn + s] = ent;
            out[3 * Bn + s] = valbuf[tid];
        }
    }
}

extern "C" void kernel_launch(void* const* d_in, const int* in_sizes, int n_in,
                              void* d_out, int out_size) {
    const float* x    = (const float*)d_in[0];
    const int*   act  = (const int*)  d_in[1];
    const float* W1   = (const float*)d_in[2];
    const float* b1   = (const float*)d_in[3];
    const float* W2   = (const float*)d_in[4];
    const float* b2   = (const float*)d_in[5];
    const float* Wh   = (const float*)d_in[6];
    const float* bh   = (const float*)d_in[7];
    const float* Wc1  = (const float*)d_in[8];
    const float* bc1  = (const float*)d_in[9];
    const float* Wc2  = (const float*)d_in[10];
    const float* bc2  = (const float*)d_in[11];
    const float* Wc3  = (const float*)d_in[12];
    const float* bc3  = (const float*)d_in[13];
    float* out = (float*)d_out;

    const int Bn   = in_sizes[1];
    const int grid = (Bn + ROWS - 1) / ROWS;

    agent_mma<<<grid, BLOCK>>>(x, act, W1, b1, W2, b2, Wh, bh,
                               Wc1, bc1, Wc2, bc2, Wc3, bc3, out, Bn);
}

// round 5
// speedup vs baseline: 3.8011x; 1.7549x over previous
#include <cuda_runtime.h>
#include <math.h>
#include <stdint.h>

#define OBSD 194
#define HD   64
#define AD   5
#define ED   3
#define BLOCK 512
#define ROWS  128
#define NCH1  7
#define XSTR  40                     // xs row stride in floats (conflict-free frag loads)
#define G1F   (NCH1 * 4096)          // 28672 floats: layer1 B fragment image
#define GTOT  (G1F + 2 * 4096)      // + W2, Wc2 images

__device__ __align__(16) float g_b[GTOT];

__device__ __forceinline__ float tf32r(float f) {
    uint32_t r; asm("cvt.rna.tf32.f32 %0, %1;" : "=r"(r) : "f"(f));
    return __uint_as_float(r);
}
__device__ __forceinline__ float tanha(float x) {
    float y; asm("tanh.approx.f32 %0, %1;" : "=f"(y) : "f"(x)); return y;
}
__device__ __forceinline__ void mma8(float* c, uint32_t a0, uint32_t a1, uint32_t a2,
                                     uint32_t a3, uint32_t b0, uint32_t b1) {
    asm volatile("mma.sync.aligned.m16n8k8.row.col.f32.tf32.tf32.f32 "
                 "{%0,%1,%2,%3},{%4,%5,%6,%7},{%8,%9},{%0,%1,%2,%3};"
                 : "+f"(c[0]), "+f"(c[1]), "+f"(c[2]), "+f"(c[3])
                 : "r"(a0), "r"(a1), "r"(a2), "r"(a3), "r"(b0), "r"(b1));
}
#define F2U(x) __float_as_uint(x)

// ---------- prep: bake B operands into per-lane fragment order (tf32-rounded) ----------
// layer1 img[c][k8][nt][lane][half] = W[32c+8k8+tg+4*half][8nt+g],  W = [W1|Wc1] cols
// layer2 img[mat][kh][k8][nt][lane][half] = Wm[32kh+8k8+tg+4*half][8nt+g]
__global__ void prep_b(const float* __restrict__ W1, const float* __restrict__ Wc1,
                       const float* __restrict__ W2, const float* __restrict__ Wc2) {
    int idx = blockIdx.x * blockDim.x + threadIdx.x;
    if (idx >= GTOT) return;
    float v = 0.f;
    if (idx < G1F) {
        int c  = idx >> 12;
        int r  = idx & 4095;
        int k8 = r >> 10, rr = r & 1023;
        int nt = rr >> 6, q = rr & 63;
        int lane = q >> 1, half = q & 1;
        int g = lane >> 2, tg = lane & 3;
        int n = 8 * nt + g;
        int k = 32 * c + 8 * k8 + tg + 4 * half;
        if (k < OBSD) v = (n < HD) ? W1[k * HD + n] : Wc1[k * HD + n - HD];
    } else {
        int t = idx - G1F;
        int mat = t >> 12;
        int r = t & 4095;
        int kh = r >> 11, r2 = r & 2047;
        int k8 = r2 >> 9, r3 = r2 & 511;
        int nt = r3 >> 6, q = r3 & 63;
        int lane = q >> 1, half = q & 1;
        int g = lane >> 2, tg = lane & 3;
        int n = 8 * nt + g;
        int k = 32 * kh + 8 * k8 + tg + 4 * half;
        v = (mat ? Wc2 : W2)[k * HD + n];
    }
    g_b[idx] = tf32r(v);
}

// ---------- main ----------
__global__ void __launch_bounds__(BLOCK)
agent_mma(const float* __restrict__ x,   const int* __restrict__ action,
          const float* __restrict__ b1,  const float* __restrict__ b2,
          const float* __restrict__ Wh,  const float* __restrict__ bh,
          const float* __restrict__ bc1, const float* __restrict__ bc2,
          const float* __restrict__ Wc3, const float* __restrict__ bc3,
          float* __restrict__ out, int Bn)
{
    __shared__ __align__(16) float spool[ROWS * XSTR + 4096];  // xs | bbuf (36.9KB)
    __shared__ float whs[ED * HD * AD];
    __shared__ float bhs[16];
    __shared__ float b1s[HD], b2s[HD], bc1s[HD], bc2s[HD], wc3s[HD];
    __shared__ float valbuf[ROWS];

    float* xs   = spool;
    float* bbuf = spool + ROWS * XSTR;

    const int tid   = threadIdx.x;
    const int lane  = tid & 31;
    const int warp  = tid >> 5;
    const int warpM = warp & 7;
    const int warpN = warp >> 3;          // 0 / 1 : n-half
    const int g     = lane >> 2;
    const int tg    = lane & 3;
    const int rb    = warpM * 16;
    const int s0    = blockIdx.x * ROWS;

    // per-thread staging geometry (k fixed across iterations since 512 % 32 == 0)
    const int kst   = tid & 31;           // staged k within chunk
    const int rbase = tid >> 5;           // row base; rows rbase + 16*it
    const int jst   = kst & 7;
    const int pst   = (jst < 4) ? 2 * jst : 2 * jst - 7;     // permuted col
    const int xoff  = (kst >> 3) * 8 + pst;
    // H-staging permuted columns for this thread
    const int j0 = 2 * tg,     p0 = (j0 < 4) ? 2 * j0 : 2 * j0 - 7;
    const int j1 = 2 * tg + 1, p1 = (j1 < 4) ? 2 * j1 : 2 * j1 - 7;

    for (int i = tid; i < ED * HD * AD; i += BLOCK) whs[i] = Wh[i];
    if (tid < ED * AD) bhs[tid] = bh[tid];
    if (tid < HD) {
        b1s[tid] = b1[tid];   b2s[tid] = b2[tid];
        bc1s[tid] = bc1[tid]; bc2s[tid] = bc2[tid]; wc3s[tid] = Wc3[tid];
    }
    const float bc3v = __ldg(&bc3[0]);

    float acc[8][4];
    #pragma unroll
    for (int nt = 0; nt < 8; nt++)
        #pragma unroll
        for (int i = 0; i < 4; i++) acc[nt][i] = 0.f;

    // prefetch regs
    float  xp[8];
    float4 bp[2];
    const float4* gb4 = (const float4*)g_b;

    // prologue: chunk 0
    {
        #pragma unroll
        for (int it = 0; it < 8; it++) {
            int row = rbase + 16 * it;
            int srow = s0 + row; if (srow >= Bn) srow = Bn - 1;
            int col = kst;                                    // 32*0 + kst
            xp[it] = (col < OBSD) ? __ldg(&x[(size_t)srow * OBSD + col]) : 0.f;
        }
        bp[0] = __ldg(&gb4[tid]);
        bp[1] = __ldg(&gb4[tid + 512]);
    }

    // ================= GEMM1: C[128x128] = X @ [W1|Wc1], 7 chunks =================
    for (int c = 0; c < NCH1; c++) {
        __syncthreads();
        #pragma unroll
        for (int it = 0; it < 8; it++)
            xs[(rbase + 16 * it) * XSTR + xoff] = tf32r(xp[it]);
        ((float4*)bbuf)[tid]       = bp[0];
        ((float4*)bbuf)[tid + 512] = bp[1];
        __syncthreads();

        if (c < NCH1 - 1) {   // prefetch next chunk while MMAs run
            const int cn = c + 1;
            #pragma unroll
            for (int it = 0; it < 8; it++) {
                int row = rbase + 16 * it;
                int srow = s0 + row; if (srow >= Bn) srow = Bn - 1;
                int col = 32 * cn + kst;
                xp[it] = (col < OBSD) ? __ldg(&x[(size_t)srow * OBSD + col]) : 0.f;
            }
            bp[0] = __ldg(&gb4[cn * 1024 + tid]);
            bp[1] = __ldg(&gb4[cn * 1024 + tid + 512]);
        }

        #pragma unroll
        for (int k8 = 0; k8 < 4; k8++) {
            float2 aL = *(const float2*)&xs[(rb + g)     * XSTR + k8 * 8 + 2 * tg];
            float2 aH = *(const float2*)&xs[(rb + g + 8) * XSTR + k8 * 8 + 2 * tg];
            const float2* bpf = (const float2*)&bbuf[k8 * 1024 + warpN * 512 + lane * 2];
            #pragma unroll
            for (int nt = 0; nt < 8; nt++) {
                float2 bv = bpf[nt * 32];
                mma8(acc[nt], F2U(aL.x), F2U(aH.x), F2U(aL.y), F2U(aH.y),
                     F2U(bv.x), F2U(bv.y));
            }
        }
    }

    // epilogue1: bias + tanh in place (warpN0 = actor H, warpN1 = critic H)
    {
        const float* bA = warpN ? bc1s : b1s;
        #pragma unroll
        for (int nt = 0; nt < 8; nt++) {
            int nl = 8 * nt + 2 * tg;
            float ba0 = bA[nl], ba1 = bA[nl + 1];
            acc[nt][0] = tanha(acc[nt][0] + ba0);
            acc[nt][1] = tanha(acc[nt][1] + ba1);
            acc[nt][2] = tanha(acc[nt][2] + ba0);
            acc[nt][3] = tanha(acc[nt][3] + ba1);
        }
    }

    // ================= GEMM2 x2: H[128x64] @ W[64x64] =================
    float feat[4][4];
    float vr0 = 0.f, vr1 = 0.f;

    #pragma unroll
    for (int p = 0; p < 2; p++) {
        float acc2[4][4];
        #pragma unroll
        for (int nt = 0; nt < 4; nt++)
            #pragma unroll
            for (int i = 0; i < 4; i++) acc2[nt][i] = 0.f;

        #pragma unroll
        for (int kh = 0; kh < 2; kh++) {
            __syncthreads();
            if (warpN == p) {
                #pragma unroll
                for (int q = 0; q < 4; q++) {
                    int ntp = kh * 4 + q;
                    int base0 = (rb + g)     * XSTR + q * 8;
                    int base1 = (rb + g + 8) * XSTR + q * 8;
                    xs[base0 + p0] = tf32r(acc[ntp][0]);
                    xs[base0 + p1] = tf32r(acc[ntp][1]);
                    xs[base1 + p0] = tf32r(acc[ntp][2]);
                    xs[base1 + p1] = tf32r(acc[ntp][3]);
                }
            }
            ((float4*)bbuf)[tid] = __ldg(&gb4[(G1F >> 2) + p * 1024 + kh * 512 + tid]);
            __syncthreads();

            #pragma unroll
            for (int k8 = 0; k8 < 4; k8++) {
                float2 aL = *(const float2*)&xs[(rb + g)     * XSTR + k8 * 8 + 2 * tg];
                float2 aH = *(const float2*)&xs[(rb + g + 8) * XSTR + k8 * 8 + 2 * tg];
                const float2* bpf = (const float2*)&bbuf[k8 * 512 + warpN * 256 + lane * 2];
                #pragma unroll
                for (int nt = 0; nt < 4; nt++) {
                    float2 bv = bpf[nt * 32];
                    mma8(acc2[nt], F2U(aL.x), F2U(aH.x), F2U(aL.y), F2U(aH.y),
                         F2U(bv.x), F2U(bv.y));
                }
            }
        }

        if (p == 0) {
            #pragma unroll
            for (int nt = 0; nt < 4; nt++) {
                int n0 = 32 * warpN + 8 * nt + 2 * tg;
                feat[nt][0] = tanha(acc2[nt][0] + b2s[n0]);
                feat[nt][1] = tanha(acc2[nt][1] + b2s[n0 + 1]);
                feat[nt][2] = tanha(acc2[nt][2] + b2s[n0]);
                feat[nt][3] = tanha(acc2[nt][3] + b2s[n0 + 1]);
            }
        } else {
            #pragma unroll
            for (int nt = 0; nt < 4; nt++) {
                int n0 = 32 * warpN + 8 * nt + 2 * tg;
                vr0 = fmaf(tanha(acc2[nt][0] + bc2s[n0]),     wc3s[n0],     vr0);
                vr0 = fmaf(tanha(acc2[nt][1] + bc2s[n0 + 1]), wc3s[n0 + 1], vr0);
                vr1 = fmaf(tanha(acc2[nt][2] + bc2s[n0]),     wc3s[n0],     vr1);
                vr1 = fmaf(tanha(acc2[nt][3] + bc2s[n0 + 1]), wc3s[n0 + 1], vr1);
            }
        }
    }

    // value: reduce over quad, then across the two n-halves
    vr0 += __shfl_xor_sync(0xFFFFFFFF, vr0, 1);
    vr0 += __shfl_xor_sync(0xFFFFFFFF, vr0, 2);
    vr1 += __shfl_xor_sync(0xFFFFFFFF, vr1, 1);
    vr1 += __shfl_xor_sync(0xFFFFFFFF, vr1, 2);
    __syncthreads();
    if (warpN == 0 && tg == 0) {
        valbuf[rb + g]     = vr0 + bc3v;
        valbuf[rb + g + 8] = vr1 + bc3v;
    }
    __syncthreads();
    if (warpN == 1 && tg == 0) {
        valbuf[rb + g]     += vr0;
        valbuf[rb + g + 8] += vr1;
    }

    // feat fragments -> smem pool (stride 65, conflict-free row reads)
    float* fbuf = spool;
    #pragma unroll
    for (int nt = 0; nt < 4; nt++) {
        int n0 = 32 * warpN + 8 * nt + 2 * tg;
        fbuf[(rb + g)     * 65 + n0]     = feat[nt][0];
        fbuf[(rb + g)     * 65 + n0 + 1] = feat[nt][1];
        fbuf[(rb + g + 8) * 65 + n0]     = feat[nt][2];
        fbuf[(rb + g + 8) * 65 + n0 + 1] = feat[nt][3];
    }
    __syncthreads();

    // ================= per-sample head =================
    if (tid < ROWS) {
        int s = s0 + tid;
        int sr = (s < Bn) ? s : (Bn - 1);
        const float* xrow = x + (size_t)sr * OBSD;
        float x0 = __ldg(&xrow[0]), x1v = __ldg(&xrow[1]), x2v = __ldg(&xrow[2]);
        int ev = 0; float bx = x0;
        if (x1v > bx) { bx = x1v; ev = 1; }
        if (x2v > bx) { ev = 2; }

        float lg[AD];
        #pragma unroll
        for (int a = 0; a < AD; a++) lg[a] = bhs[ev * AD + a];
        const float* fr  = &fbuf[tid * 65];
        const float* whe = &whs[ev * HD * AD];
        #pragma unroll 8
        for (int k = 0; k < HD; k++) {
            float fk = fr[k];
            #pragma unroll
            for (int a = 0; a < AD; a++) lg[a] = fmaf(fk, whe[k * AD + a], lg[a]);
        }
        float m = lg[0];
        #pragma unroll
        for (int a = 1; a < AD; a++) m = fmaxf(m, lg[a]);
        float se = 0.f;
        #pragma unroll
        for (int a = 0; a < AD; a++) se += __expf(lg[a] - m);
        float lse = __logf(se);
        float ent = 0.f;
        #pragma unroll
        for (int a = 0; a < AD; a++) {
            float lp = lg[a] - m - lse;
            ent -= __expf(lp) * lp;
        }
        int   act  = __ldg(&action[sr]);
        float logp = lg[act] - m - lse;

        if (s < Bn) {
            out[s]          = (float)act;
            out[Bn + s]     = logp;
            out[2 * Bn + s] = ent;
            out[3 * Bn + s] = valbuf[tid];
        }
    }
}

extern "C" void kernel_launch(void* const* d_in, const int* in_sizes, int n_in,
                              void* d_out, int out_size) {
    const float* x    = (const float*)d_in[0];
    const int*   act  = (const int*)  d_in[1];
    const float* W1   = (const float*)d_in[2];
    const float* b1   = (const float*)d_in[3];
    const float* W2   = (const float*)d_in[4];
    const float* b2   = (const float*)d_in[5];
    const float* Wh   = (const float*)d_in[6];
    const float* bh   = (const float*)d_in[7];
    const float* Wc1  = (const float*)d_in[8];
    const float* bc1  = (const float*)d_in[9];
    const float* Wc2  = (const float*)d_in[10];
    const float* bc2  = (const float*)d_in[11];
    const float* Wc3  = (const float*)d_in[12];
    const float* bc3  = (const float*)d_in[13];
    float* out = (float*)d_out;

    const int Bn = in_sizes[1];

    prep_b<<<(GTOT + 255) / 256, 256>>>(W1, Wc1, W2, Wc2);

    const int grid = (Bn + ROWS - 1) / ROWS;
    agent_mma<<<grid, BLOCK>>>(x, act, b1, b2, Wh, bh, bc1, bc2, Wc3, bc3, out, Bn);
}

// round 6
// speedup vs baseline: 4.8387x; 1.2730x over previous
#include <cuda_runtime.h>
#include <math.h>
#include <stdint.h>

#define OBSD 194
#define HD   64
#define AD   5
#define ED   3
#define BLOCK 256
#define ROWS  128
#define NCH1  7
#define XSTR  40
#define G1F   (NCH1 * 4096)          // GEMM1 B image: 7 chunks x [h][ntAll16][lane][q]
#define GTOT  (G1F + 2 * 4096)       // + W2, Wc2 images
#define PERM(j) ((j) < 4 ? 2*(j) : 2*(j) - 7)

__device__ __align__(16) float g_b[GTOT];

__device__ __forceinline__ float tf32r(float f) {
    uint32_t r; asm("cvt.rna.tf32.f32 %0, %1;" : "=r"(r) : "f"(f));
    return __uint_as_float(r);
}
__device__ __forceinline__ float tanha(float x) {
    float y; asm("tanh.approx.f32 %0, %1;" : "=f"(y) : "f"(x)); return y;
}
__device__ __forceinline__ void mma8(float* c, uint32_t a0, uint32_t a1, uint32_t a2,
                                     uint32_t a3, uint32_t b0, uint32_t b1) {
    asm volatile("mma.sync.aligned.m16n8k8.row.col.f32.tf32.tf32.f32 "
                 "{%0,%1,%2,%3},{%4,%5,%6,%7},{%8,%9},{%0,%1,%2,%3};"
                 : "+f"(c[0]), "+f"(c[1]), "+f"(c[2]), "+f"(c[3])
                 : "r"(a0), "r"(a1), "r"(a2), "r"(a3), "r"(b0), "r"(b1));
}
#define F2U(x) __float_as_uint(x)

// ---------- prep: bake B operands as float4-fragment images (tf32-rounded) ----------
// GEMM1: float idx = c*4096 + h*2048 + ntAll*128 + lane*4 + q
//   k8 = 2h + (q>>1); k = 32c + 8*k8 + tg + 4*(q&1); n = 8*ntAll + g;  [W1|Wc1]
// GEMM2: G1F + mat*4096 + kh*2048 + h*1024 + ntAll*128 + lane*4 + q   (W2, Wc2)
__global__ void prep_b(const float* __restrict__ W1, const float* __restrict__ Wc1,
                       const float* __restrict__ W2, const float* __restrict__ Wc2) {
    int idx = blockIdx.x * blockDim.x + threadIdx.x;
    if (idx >= GTOT) return;
    int lane = (idx >> 2) & 31;
    int q    = idx & 3;
    int g = lane >> 2, tg = lane & 3;
    float v = 0.f;
    if (idx < G1F) {
        int c     = idx >> 12;
        int h     = (idx >> 11) & 1;
        int ntAll = (idx >> 7) & 15;
        int k8 = 2 * h + (q >> 1);
        int k  = 32 * c + 8 * k8 + tg + 4 * (q & 1);
        int n  = 8 * ntAll + g;
        if (k < OBSD) v = (n < HD) ? W1[k * HD + n] : Wc1[k * HD + n - HD];
    } else {
        int t     = idx - G1F;
        int mat   = t >> 12;
        int kh    = (t >> 11) & 1;
        int h     = (t >> 10) & 1;
        int ntAll = (t >> 7) & 7;
        int k8 = 2 * h + (q >> 1);
        int k  = 32 * kh + 8 * k8 + tg + 4 * (q & 1);
        int n  = 8 * ntAll + g;
        v = (mat ? Wc2 : W2)[k * HD + n];
    }
    g_b[idx] = tf32r(v);
}

// ---------- main ----------
__global__ void __launch_bounds__(BLOCK, 2)
agent_mma(const float* __restrict__ x,   const int* __restrict__ action,
          const float* __restrict__ b1,  const float* __restrict__ b2,
          const float* __restrict__ Wh,  const float* __restrict__ bh,
          const float* __restrict__ bc1, const float* __restrict__ bc2,
          const float* __restrict__ Wc3, const float* __restrict__ bc3,
          float* __restrict__ out, int Bn)
{
    __shared__ __align__(16) float spool[ROWS * XSTR + 4096];  // xs | bbuf
    __shared__ float whs[ED * HD * AD];
    __shared__ float bhs[16];
    __shared__ float b1s[HD], b2s[HD], bc1s[HD], bc2s[HD], wc3s[HD];
    __shared__ float valbuf[ROWS];

    float* xs   = spool;
    float* bbuf = spool + ROWS * XSTR;
    float4* bbuf4 = (float4*)bbuf;
    const float4* gb4 = (const float4*)g_b;
    const float2* xs2 = (const float2*)xs;

    const int tid   = threadIdx.x;
    const int lane  = tid & 31;
    const int warp  = tid >> 5;
    const int warpM = warp & 3;
    const int warpN = warp >> 2;
    const int g     = lane >> 2;
    const int tg    = lane & 3;
    const int rb2   = warpM * 32;
    const int s0    = blockIdx.x * ROWS;

    // x staging geometry: thread covers k = {2*kpair, 2*kpair+1}, rows rowb + 16*it
    const int kpair = tid & 15;
    const int rowb  = tid >> 4;
    const int j0    = (2 * kpair) & 7;
    const int k80   = (2 * kpair) >> 3;
    const int o0    = k80 * 8 + PERM(j0);
    const int o1    = k80 * 8 + PERM(j0 + 1);
    // H staging perms (logical j = 2tg, 2tg+1)
    const int p0 = PERM(2 * tg);
    const int p1 = PERM(2 * tg + 1);

    for (int i = tid; i < ED * HD * AD; i += BLOCK) whs[i] = Wh[i];
    if (tid < ED * AD) bhs[tid] = bh[tid];
    if (tid < HD) {
        b1s[tid] = b1[tid];   b2s[tid] = b2[tid];
        bc1s[tid] = bc1[tid]; bc2s[tid] = bc2[tid]; wc3s[tid] = Wc3[tid];
    }
    const float bc3v = __ldg(&bc3[0]);

    float acc[2][8][4];
    #pragma unroll
    for (int t = 0; t < 2; t++)
        #pragma unroll
        for (int nt = 0; nt < 8; nt++)
            #pragma unroll
            for (int i = 0; i < 4; i++) acc[t][nt][i] = 0.f;

    // x prefetch for chunk 0
    float2 xp[8];
    #pragma unroll
    for (int it = 0; it < 8; it++) {
        int row = rowb + 16 * it;
        int srow = s0 + row; if (srow >= Bn) srow = Bn - 1;
        xp[it] = __ldg((const float2*)(x + (size_t)srow * OBSD + 2 * kpair));
    }

    // ================= GEMM1: C[128x128] = X @ [W1|Wc1], 7 chunks =================
    for (int c = 0; c < NCH1; c++) {
        __syncthreads();
        #pragma unroll
        for (int it = 0; it < 8; it++) {
            int rbase = (rowb + 16 * it) * XSTR;
            xs[rbase + o0] = tf32r(xp[it].x);
            xs[rbase + o1] = tf32r(xp[it].y);
        }
        #pragma unroll
        for (int i = 0; i < 4; i++)
            bbuf4[tid + 256 * i] = __ldg(&gb4[c * 1024 + tid + 256 * i]);
        __syncthreads();

        if (c < NCH1 - 1) {
            int col0 = 32 * (c + 1) + 2 * kpair;
            #pragma unroll
            for (int it = 0; it < 8; it++) {
                int row = rowb + 16 * it;
                int srow = s0 + row; if (srow >= Bn) srow = Bn - 1;
                xp[it] = (col0 < OBSD)
                    ? __ldg((const float2*)(x + (size_t)srow * OBSD + col0))
                    : make_float2(0.f, 0.f);
            }
        }

        #pragma unroll
        for (int h = 0; h < 2; h++) {
            float2 aL[2][2], aH[2][2];
            #pragma unroll
            for (int t = 0; t < 2; t++)
                #pragma unroll
                for (int e = 0; e < 2; e++) {
                    int ko = (2 * h + e) * 4 + tg;
                    aL[t][e] = xs2[(rb2 + 16 * t + g)     * 20 + ko];
                    aH[t][e] = xs2[(rb2 + 16 * t + g + 8) * 20 + ko];
                }
            #pragma unroll
            for (int nt = 0; nt < 8; nt++) {
                float4 bq = bbuf4[h * 512 + (warpN * 8 + nt) * 32 + lane];
                mma8(acc[0][nt], F2U(aL[0][0].x), F2U(aH[0][0].x),
                     F2U(aL[0][0].y), F2U(aH[0][0].y), F2U(bq.x), F2U(bq.y));
                mma8(acc[1][nt], F2U(aL[1][0].x), F2U(aH[1][0].x),
                     F2U(aL[1][0].y), F2U(aH[1][0].y), F2U(bq.x), F2U(bq.y));
                mma8(acc[0][nt], F2U(aL[0][1].x), F2U(aH[0][1].x),
                     F2U(aL[0][1].y), F2U(aH[0][1].y), F2U(bq.z), F2U(bq.w));
                mma8(acc[1][nt], F2U(aL[1][1].x), F2U(aH[1][1].x),
                     F2U(aL[1][1].y), F2U(aH[1][1].y), F2U(bq.z), F2U(bq.w));
            }
        }
    }

    // epilogue1: bias + tanh (warpN0 holds actor H cols 0..63, warpN1 critic H)
    {
        const float* bA = warpN ? bc1s : b1s;
        #pragma unroll
        for (int t = 0; t < 2; t++)
            #pragma unroll
            for (int nt = 0; nt < 8; nt++) {
                int n0 = 8 * nt + 2 * tg;
                acc[t][nt][0] = tanha(acc[t][nt][0] + bA[n0]);
                acc[t][nt][1] = tanha(acc[t][nt][1] + bA[n0 + 1]);
                acc[t][nt][2] = tanha(acc[t][nt][2] + bA[n0]);
                acc[t][nt][3] = tanha(acc[t][nt][3] + bA[n0 + 1]);
            }
    }

    // ================= GEMM2: critic pass (mat=1) then actor pass (mat=0) =================
    #pragma unroll 1
    for (int pp = 0; pp < 2; pp++) {
        const int mat = (pp == 0) ? 1 : 0;     // critic first (caps reg pressure)
        float acc2[2][4][4];
        #pragma unroll
        for (int t = 0; t < 2; t++)
            #pragma unroll
            for (int nt = 0; nt < 4; nt++)
                #pragma unroll
                for (int i = 0; i < 4; i++) acc2[t][nt][i] = 0.f;

        #pragma unroll
        for (int kh = 0; kh < 2; kh++) {
            __syncthreads();
            if (warpN == mat) {      // owner warps stage their H chunk
                #pragma unroll
                for (int t = 0; t < 2; t++)
                    #pragma unroll
                    for (int q = 0; q < 4; q++) {
                        int ntsel = 4 * kh + q;
                        int r0 = (rb2 + 16 * t + g) * XSTR + q * 8;
                        int r1 = (rb2 + 16 * t + g + 8) * XSTR + q * 8;
                        xs[r0 + p0] = tf32r(acc[t][ntsel][0]);
                        xs[r0 + p1] = tf32r(acc[t][ntsel][1]);
                        xs[r1 + p0] = tf32r(acc[t][ntsel][2]);
                        xs[r1 + p1] = tf32r(acc[t][ntsel][3]);
                    }
            }
            #pragma unroll
            for (int i = 0; i < 2; i++)
                bbuf4[tid + 256 * i] =
                    __ldg(&gb4[(G1F >> 2) + mat * 1024 + kh * 512 + tid + 256 * i]);
            __syncthreads();

            #pragma unroll
            for (int h = 0; h < 2; h++) {
                float2 aL[2][2], aH[2][2];
                #pragma unroll
                for (int t = 0; t < 2; t++)
                    #pragma unroll
                    for (int e = 0; e < 2; e++) {
                        int ko = (2 * h + e) * 4 + tg;
                        aL[t][e] = xs2[(rb2 + 16 * t + g)     * 20 + ko];
                        aH[t][e] = xs2[(rb2 + 16 * t + g + 8) * 20 + ko];
                    }
                #pragma unroll
                for (int nt = 0; nt < 4; nt++) {
                    float4 bq = bbuf4[h * 256 + (warpN * 4 + nt) * 32 + lane];
                    mma8(acc2[0][nt], F2U(aL[0][0].x), F2U(aH[0][0].x),
                         F2U(aL[0][0].y), F2U(aH[0][0].y), F2U(bq.x), F2U(bq.y));
                    mma8(acc2[1][nt], F2U(aL[1][0].x), F2U(aH[1][0].x),
                         F2U(aL[1][0].y), F2U(aH[1][0].y), F2U(bq.x), F2U(bq.y));
                    mma8(acc2[0][nt], F2U(aL[0][1].x), F2U(aH[0][1].x),
                         F2U(aL[0][1].y), F2U(aH[0][1].y), F2U(bq.z), F2U(bq.w));
                    mma8(acc2[1][nt], F2U(aL[1][1].x), F2U(aH[1][1].x),
                         F2U(aL[1][1].y), F2U(aH[1][1].y), F2U(bq.z), F2U(bq.w));
                }
            }
        }

        if (mat == 1) {
            // critic: value partials, reduce over quad, combine warpN halves
            float vr[4] = {0.f, 0.f, 0.f, 0.f};
            #pragma unroll
            for (int t = 0; t < 2; t++)
                #pragma unroll
                for (int nt = 0; nt < 4; nt++) {
                    int n0 = warpN * 32 + 8 * nt + 2 * tg;
                    vr[2*t]   = fmaf(tanha(acc2[t][nt][0] + bc2s[n0]),     wc3s[n0],     vr[2*t]);
                    vr[2*t]   = fmaf(tanha(acc2[t][nt][1] + bc2s[n0 + 1]), wc3s[n0 + 1], vr[2*t]);
                    vr[2*t+1] = fmaf(tanha(acc2[t][nt][2] + bc2s[n0]),     wc3s[n0],     vr[2*t+1]);
                    vr[2*t+1] = fmaf(tanha(acc2[t][nt][3] + bc2s[n0 + 1]), wc3s[n0 + 1], vr[2*t+1]);
                }
            #pragma unroll
            for (int i = 0; i < 4; i++) {
                vr[i] += __shfl_xor_sync(0xFFFFFFFF, vr[i], 1);
                vr[i] += __shfl_xor_sync(0xFFFFFFFF, vr[i], 2);
            }
            __syncthreads();
            if (warpN == 0 && tg == 0) {
                valbuf[rb2 + g]      = vr[0] + bc3v;
                valbuf[rb2 + g + 8]  = vr[1];
                valbuf[rb2 + g + 16] = vr[2];
                valbuf[rb2 + g + 24] = vr[3];
            }
            __syncthreads();
            if (warpN == 1 && tg == 0) {
                valbuf[rb2 + g]      += vr[0];
                valbuf[rb2 + g + 8]  += vr[1] + bc3v;
                valbuf[rb2 + g + 16] += vr[2] + bc3v;
                valbuf[rb2 + g + 24] += vr[3] + bc3v;
            }
        } else {
            // actor: feat -> fbuf (stride 65), after all consumers done with spool
            __syncthreads();
            float* fbuf = spool;
            #pragma unroll
            for (int t = 0; t < 2; t++)
                #pragma unroll
                for (int nt = 0; nt < 4; nt++) {
                    int n0 = warpN * 32 + 8 * nt + 2 * tg;
                    int r0 = (rb2 + 16 * t + g) * 65;
                    int r1 = (rb2 + 16 * t + g + 8) * 65;
                    fbuf[r0 + n0]     = tanha(acc2[t][nt][0] + b2s[n0]);
                    fbuf[r0 + n0 + 1] = tanha(acc2[t][nt][1] + b2s[n0 + 1]);
                    fbuf[r1 + n0]     = tanha(acc2[t][nt][2] + b2s[n0]);
                    fbuf[r1 + n0 + 1] = tanha(acc2[t][nt][3] + b2s[n0 + 1]);
                }
            __syncthreads();
        }
    }

    // ================= per-sample head =================
    if (tid < ROWS) {
        const float* fbuf = spool;
        int s = s0 + tid;
        int sr = (s < Bn) ? s : (Bn - 1);
        const float* xrow = x + (size_t)sr * OBSD;
        float x0 = __ldg(&xrow[0]), x1v = __ldg(&xrow[1]), x2v = __ldg(&xrow[2]);
        int ev = 0; float bx = x0;
        if (x1v > bx) { bx = x1v; ev = 1; }
        if (x2v > bx) { ev = 2; }

        float lg[AD];
        #pragma unroll
        for (int a = 0; a < AD; a++) lg[a] = bhs[ev * AD + a];
        const float* fr  = &fbuf[tid * 65];
        const float* whe = &whs[ev * HD * AD];
        #pragma unroll 8
        for (int k = 0; k < HD; k++) {
            float fk = fr[k];
            #pragma unroll
            for (int a = 0; a < AD; a++) lg[a] = fmaf(fk, whe[k * AD + a], lg[a]);
        }
        float m = lg[0];
        #pragma unroll
        for (int a = 1; a < AD; a++) m = fmaxf(m, lg[a]);
        float se = 0.f;
        #pragma unroll
        for (int a = 0; a < AD; a++) se += __expf(lg[a] - m);
        float lse = __logf(se);
        float ent = 0.f;
        #pragma unroll
        for (int a = 0; a < AD; a++) {
            float lp = lg[a] - m - lse;
            ent -= __expf(lp) * lp;
        }
        int   act  = __ldg(&action[sr]);
        float logp = lg[act] - m - lse;

        if (s < Bn) {
            out[s]          = (float)act;
            out[Bn + s]     = logp;
            out[2 * Bn + s] = ent;
            out[3 * Bn + s] = valbuf[tid];
        }
    }
}

extern "C" void kernel_launch(void* const* d_in, const int* in_sizes, int n_in,
                              void* d_out, int out_size) {
    const float* x    = (const float*)d_in[0];
    const int*   act  = (const int*)  d_in[1];
    const float* W1   = (const float*)d_in[2];
    const float* b1   = (const float*)d_in[3];
    const float* W2   = (const float*)d_in[4];
    const float* b2   = (const float*)d_in[5];
    const float* Wh   = (const float*)d_in[6];
    const float* bh   = (const float*)d_in[7];
    const float* Wc1  = (const float*)d_in[8];
    const float* bc1  = (const float*)d_in[9];
    const float* Wc2  = (const float*)d_in[10];
    const float* bc2  = (const float*)d_in[11];
    const float* Wc3  = (const float*)d_in[12];
    const float* bc3  = (const float*)d_in[13];
    float* out = (float*)d_out;

    const int Bn = in_sizes[1];

    prep_b<<<(GTOT + 255) / 256, 256>>>(W1, Wc1, W2, Wc2);

    const int grid = (Bn + ROWS - 1) / ROWS;
    agent_mma<<<grid, BLOCK>>>(x, act, b1, b2, Wh, bh, bc1, bc2, Wc3, bc3, out, Bn);
}

// round 7
// speedup vs baseline: 4.8402x; 1.0003x over previous
#include <cuda_runtime.h>
#include <math.h>
#include <stdint.h>

#define OBSD 194
#define HD   64
#define AD   5
#define ED   3
#define BLOCK 256
#define ROWS  128
#define NCH1  7
#define XSTR  40
#define XBUF  (ROWS * XSTR)          // 5120 floats per staging buffer
#define G1F   (NCH1 * 4096)
#define GTOT  (G1F + 2 * 4096)
#define PERM(j) ((j) < 4 ? 2*(j) : 2*(j) - 7)

__device__ __align__(16) float g_b[GTOT];

__device__ __forceinline__ float tf32r(float f) {
    uint32_t r; asm("cvt.rna.tf32.f32 %0, %1;" : "=r"(r) : "f"(f));
    return __uint_as_float(r);
}
__device__ __forceinline__ float tanha(float x) {
    float y; asm("tanh.approx.f32 %0, %1;" : "=f"(y) : "f"(x)); return y;
}
__device__ __forceinline__ void mma8(float* c, uint32_t a0, uint32_t a1, uint32_t a2,
                                     uint32_t a3, uint32_t b0, uint32_t b1) {
    asm volatile("mma.sync.aligned.m16n8k8.row.col.f32.tf32.tf32.f32 "
                 "{%0,%1,%2,%3},{%4,%5,%6,%7},{%8,%9},{%0,%1,%2,%3};"
                 : "+f"(c[0]), "+f"(c[1]), "+f"(c[2]), "+f"(c[3])
                 : "r"(a0), "r"(a1), "r"(a2), "r"(a3), "r"(b0), "r"(b1));
}
#define F2U(x) __float_as_uint(x)

// ---------- prep: bake B operands as float4-fragment images (tf32-rounded) ----------
__global__ void prep_b(const float* __restrict__ W1, const float* __restrict__ Wc1,
                       const float* __restrict__ W2, const float* __restrict__ Wc2) {
    int idx = blockIdx.x * blockDim.x + threadIdx.x;
    if (idx >= GTOT) return;
    int lane = (idx >> 2) & 31;
    int q    = idx & 3;
    int g = lane >> 2, tg = lane & 3;
    float v = 0.f;
    if (idx < G1F) {
        int c     = idx >> 12;
        int h     = (idx >> 11) & 1;
        int ntAll = (idx >> 7) & 15;
        int k8 = 2 * h + (q >> 1);
        int k  = 32 * c + 8 * k8 + tg + 4 * (q & 1);
        int n  = 8 * ntAll + g;
        if (k < OBSD) v = (n < HD) ? W1[k * HD + n] : Wc1[k * HD + n - HD];
    } else {
        int t     = idx - G1F;
        int mat   = t >> 12;
        int kh    = (t >> 11) & 1;
        int h     = (t >> 10) & 1;
        int ntAll = (t >> 7) & 7;
        int k8 = 2 * h + (q >> 1);
        int k  = 32 * kh + 8 * k8 + tg + 4 * (q & 1);
        int n  = 8 * ntAll + g;
        v = (mat ? Wc2 : W2)[k * HD + n];
    }
    g_b[idx] = tf32r(v);
}

// ---------- main ----------
__global__ void __launch_bounds__(BLOCK, 2)
agent_mma(const float* __restrict__ x,   const int* __restrict__ action,
          const float* __restrict__ b1,  const float* __restrict__ b2,
          const float* __restrict__ Wh,  const float* __restrict__ bh,
          const float* __restrict__ bc1, const float* __restrict__ bc2,
          const float* __restrict__ Wc3, const float* __restrict__ bc3,
          float* __restrict__ out, int Bn)
{
    __shared__ __align__(16) float spool[2 * XBUF];   // two x/H staging buffers (40KB)
    __shared__ float whs[ED * HD * AD];
    __shared__ float bhs[16];
    __shared__ float b1s[HD], b2s[HD], bc1s[HD], bc2s[HD], wc3s[HD];
    __shared__ float valbuf[ROWS];

    const float4* gb4 = (const float4*)g_b;

    const int tid   = threadIdx.x;
    const int lane  = tid & 31;
    const int warp  = tid >> 5;
    const int warpM = warp & 3;
    const int warpN = warp >> 2;
    const int g     = lane >> 2;
    const int tg    = lane & 3;
    const int rb2   = warpM * 32;
    const int s0    = blockIdx.x * ROWS;

    // x staging geometry
    const int kpair = tid & 15;
    const int rowb  = tid >> 4;
    const int j0    = (2 * kpair) & 7;
    const int k80   = (2 * kpair) >> 3;
    const int o0    = k80 * 8 + PERM(j0);
    const int o1    = k80 * 8 + PERM(j0 + 1);
    // H staging perms
    const int p0 = PERM(2 * tg);
    const int p1 = PERM(2 * tg + 1);

    for (int i = tid; i < ED * HD * AD; i += BLOCK) whs[i] = Wh[i];
    if (tid < ED * AD) bhs[tid] = bh[tid];
    if (tid < HD) {
        b1s[tid] = b1[tid];   b2s[tid] = b2[tid];
        bc1s[tid] = bc1[tid]; bc2s[tid] = bc2[tid]; wc3s[tid] = Wc3[tid];
    }
    const float bc3v = __ldg(&bc3[0]);

    float acc[2][8][4];
    #pragma unroll
    for (int t = 0; t < 2; t++)
        #pragma unroll
        for (int nt = 0; nt < 8; nt++)
            #pragma unroll
            for (int i = 0; i < 4; i++) acc[t][nt][i] = 0.f;

    // stage chunk 0 into buf0
    {
        #pragma unroll
        for (int it = 0; it < 8; it++) {
            int row = rowb + 16 * it;
            int srow = s0 + row; if (srow >= Bn) srow = Bn - 1;
            float2 v = __ldg((const float2*)(x + (size_t)srow * OBSD + 2 * kpair));
            spool[row * XSTR + o0] = tf32r(v.x);
            spool[row * XSTR + o1] = tf32r(v.y);
        }
    }

    // ================= GEMM1: C[128x128] = X @ [W1|Wc1], 7 chunks =================
    for (int c = 0; c < NCH1; c++) {
        float2 xq[8];
        if (c < NCH1 - 1) {                 // prefetch next chunk's x
            int col0 = 32 * (c + 1) + 2 * kpair;
            #pragma unroll
            for (int it = 0; it < 8; it++) {
                int row = rowb + 16 * it;
                int srow = s0 + row; if (srow >= Bn) srow = Bn - 1;
                xq[it] = (col0 < OBSD)
                    ? __ldg((const float2*)(x + (size_t)srow * OBSD + col0))
                    : make_float2(0.f, 0.f);
            }
        }
        __syncthreads();                    // buf[c&1] ready for all warps

        const float* xsb = spool + (c & 1) * XBUF;
        const float2* xs2 = (const float2*)xsb;
        const float4* gbc = gb4 + c * 1024 + (warpN * 8) * 32 + lane;

        #pragma unroll
        for (int h = 0; h < 2; h++) {
            float2 aL[2][2], aH[2][2];
            #pragma unroll
            for (int t = 0; t < 2; t++)
                #pragma unroll
                for (int e = 0; e < 2; e++) {
                    int ko = (2 * h + e) * 4 + tg;
                    aL[t][e] = xs2[(rb2 + 16 * t + g)     * 20 + ko];
                    aH[t][e] = xs2[(rb2 + 16 * t + g + 8) * 20 + ko];
                }
            #pragma unroll
            for (int nt = 0; nt < 8; nt++) {
                float4 bq = __ldg(gbc + h * 512 + nt * 32);
                mma8(acc[0][nt], F2U(aL[0][0].x), F2U(aH[0][0].x),
                     F2U(aL[0][0].y), F2U(aH[0][0].y), F2U(bq.x), F2U(bq.y));
                mma8(acc[1][nt], F2U(aL[1][0].x), F2U(aH[1][0].x),
                     F2U(aL[1][0].y), F2U(aH[1][0].y), F2U(bq.x), F2U(bq.y));
                mma8(acc[0][nt], F2U(aL[0][1].x), F2U(aH[0][1].x),
                     F2U(aL[0][1].y), F2U(aH[0][1].y), F2U(bq.z), F2U(bq.w));
                mma8(acc[1][nt], F2U(aL[1][1].x), F2U(aH[1][1].x),
                     F2U(aL[1][1].y), F2U(aH[1][1].y), F2U(bq.z), F2U(bq.w));
            }
        }

        if (c < NCH1 - 1) {                 // stage next chunk into the other buffer
            float* xsn = spool + ((c + 1) & 1) * XBUF;
            #pragma unroll
            for (int it = 0; it < 8; it++) {
                int rbase = (rowb + 16 * it) * XSTR;
                xsn[rbase + o0] = tf32r(xq[it].x);
                xsn[rbase + o1] = tf32r(xq[it].y);
            }
        }
    }

    // epilogue1: bias + tanh (warpN0 = actor H cols, warpN1 = critic H cols)
    {
        const float* bA = warpN ? bc1s : b1s;
        #pragma unroll
        for (int t = 0; t < 2; t++)
            #pragma unroll
            for (int nt = 0; nt < 8; nt++) {
                int n0 = 8 * nt + 2 * tg;
                acc[t][nt][0] = tanha(acc[t][nt][0] + bA[n0]);
                acc[t][nt][1] = tanha(acc[t][nt][1] + bA[n0 + 1]);
                acc[t][nt][2] = tanha(acc[t][nt][2] + bA[n0]);
                acc[t][nt][3] = tanha(acc[t][nt][3] + bA[n0 + 1]);
            }
    }

    // ================= GEMM2: critic pass (mat=1) then actor pass (mat=0) =================
    #pragma unroll 1
    for (int pp = 0; pp < 2; pp++) {
        const int mat = (pp == 0) ? 1 : 0;
        float acc2[2][4][4];
        #pragma unroll
        for (int t = 0; t < 2; t++)
            #pragma unroll
            for (int nt = 0; nt < 4; nt++)
                #pragma unroll
                for (int i = 0; i < 4; i++) acc2[t][nt][i] = 0.f;

        __syncthreads();                    // buffers free for restaging
        if (warpN == mat) {                 // owner warps stage both kh chunks of H
            #pragma unroll
            for (int kh = 0; kh < 2; kh++) {
                float* xsn = spool + kh * XBUF;
                #pragma unroll
                for (int t = 0; t < 2; t++)
                    #pragma unroll
                    for (int q = 0; q < 4; q++) {
                        int ntsel = 4 * kh + q;
                        int r0 = (rb2 + 16 * t + g) * XSTR + q * 8;
                        int r1 = (rb2 + 16 * t + g + 8) * XSTR + q * 8;
                        xsn[r0 + p0] = tf32r(acc[t][ntsel][0]);
                        xsn[r0 + p1] = tf32r(acc[t][ntsel][1]);
                        xsn[r1 + p0] = tf32r(acc[t][ntsel][2]);
                        xsn[r1 + p1] = tf32r(acc[t][ntsel][3]);
                    }
            }
        }
        __syncthreads();

        const float4* gb2 = gb4 + (G1F >> 2) + mat * 1024 + (warpN * 4) * 32 + lane;
        #pragma unroll
        for (int kh = 0; kh < 2; kh++) {
            const float2* xs2 = (const float2*)(spool + kh * XBUF);
            #pragma unroll
            for (int h = 0; h < 2; h++) {
                float2 aL[2][2], aH[2][2];
                #pragma unroll
                for (int t = 0; t < 2; t++)
                    #pragma unroll
                    for (int e = 0; e < 2; e++) {
                        int ko = (2 * h + e) * 4 + tg;
                        aL[t][e] = xs2[(rb2 + 16 * t + g)     * 20 + ko];
                        aH[t][e] = xs2[(rb2 + 16 * t + g + 8) * 20 + ko];
                    }
                #pragma unroll
                for (int nt = 0; nt < 4; nt++) {
                    float4 bq = __ldg(gb2 + kh * 512 + h * 256 + nt * 32);
                    mma8(acc2[0][nt], F2U(aL[0][0].x), F2U(aH[0][0].x),
                         F2U(aL[0][0].y), F2U(aH[0][0].y), F2U(bq.x), F2U(bq.y));
                    mma8(acc2[1][nt], F2U(aL[1][0].x), F2U(aH[1][0].x),
                         F2U(aL[1][0].y), F2U(aH[1][0].y), F2U(bq.x), F2U(bq.y));
                    mma8(acc2[0][nt], F2U(aL[0][1].x), F2U(aH[0][1].x),
                         F2U(aL[0][1].y), F2U(aH[0][1].y), F2U(bq.z), F2U(bq.w));
                    mma8(acc2[1][nt], F2U(aL[1][1].x), F2U(aH[1][1].x),
                         F2U(aL[1][1].y), F2U(aH[1][1].y), F2U(bq.z), F2U(bq.w));
                }
            }
        }

        if (mat == 1) {
            float vr[4] = {0.f, 0.f, 0.f, 0.f};
            #pragma unroll
            for (int t = 0; t < 2; t++)
                #pragma unroll
                for (int nt = 0; nt < 4; nt++) {
                    int n0 = warpN * 32 + 8 * nt + 2 * tg;
                    vr[2*t]   = fmaf(tanha(acc2[t][nt][0] + bc2s[n0]),     wc3s[n0],     vr[2*t]);
                    vr[2*t]   = fmaf(tanha(acc2[t][nt][1] + bc2s[n0 + 1]), wc3s[n0 + 1], vr[2*t]);
                    vr[2*t+1] = fmaf(tanha(acc2[t][nt][2] + bc2s[n0]),     wc3s[n0],     vr[2*t+1]);
                    vr[2*t+1] = fmaf(tanha(acc2[t][nt][3] + bc2s[n0 + 1]), wc3s[n0 + 1], vr[2*t+1]);
                }
            #pragma unroll
            for (int i = 0; i < 4; i++) {
                vr[i] += __shfl_xor_sync(0xFFFFFFFF, vr[i], 1);
                vr[i] += __shfl_xor_sync(0xFFFFFFFF, vr[i], 2);
            }
            __syncthreads();
            if (warpN == 0 && tg == 0) {
                valbuf[rb2 + g]      = vr[0] + bc3v;
                valbuf[rb2 + g + 8]  = vr[1];
                valbuf[rb2 + g + 16] = vr[2];
                valbuf[rb2 + g + 24] = vr[3];
            }
            __syncthreads();
            if (warpN == 1 && tg == 0) {
                valbuf[rb2 + g]      += vr[0];
                valbuf[rb2 + g + 8]  += vr[1] + bc3v;
                valbuf[rb2 + g + 16] += vr[2] + bc3v;
                valbuf[rb2 + g + 24] += vr[3] + bc3v;
            }
        } else {
            // actor: feat -> fbuf (stride 65), spool reuse
            __syncthreads();
            float* fbuf = spool;
            #pragma unroll
            for (int t = 0; t < 2; t++)
                #pragma unroll
                for (int nt = 0; nt < 4; nt++) {
                    int n0 = warpN * 32 + 8 * nt + 2 * tg;
                    int r0 = (rb2 + 16 * t + g) * 65;
                    int r1 = (rb2 + 16 * t + g + 8) * 65;
                    fbuf[r0 + n0]     = tanha(acc2[t][nt][0] + b2s[n0]);
                    fbuf[r0 + n0 + 1] = tanha(acc2[t][nt][1] + b2s[n0 + 1]);
                    fbuf[r1 + n0]     = tanha(acc2[t][nt][2] + b2s[n0]);
                    fbuf[r1 + n0 + 1] = tanha(acc2[t][nt][3] + b2s[n0 + 1]);
                }
            __syncthreads();
        }
    }

    // ================= per-sample head =================
    if (tid < ROWS) {
        const float* fbuf = spool;
        int s = s0 + tid;
        int sr = (s < Bn) ? s : (Bn - 1);
        const float* xrow = x + (size_t)sr * OBSD;
        float x0 = __ldg(&xrow[0]), x1v = __ldg(&xrow[1]), x2v = __ldg(&xrow[2]);
        int ev = 0; float bx = x0;
        if (x1v > bx) { bx = x1v; ev = 1; }
        if (x2v > bx) { ev = 2; }

        float lg[AD];
        #pragma unroll
        for (int a = 0; a < AD; a++) lg[a] = bhs[ev * AD + a];
        const float* fr  = &fbuf[tid * 65];
        const float* whe = &whs[ev * HD * AD];
        #pragma unroll 8
        for (int k = 0; k < HD; k++) {
            float fk = fr[k];
            #pragma unroll
            for (int a = 0; a < AD; a++) lg[a] = fmaf(fk, whe[k * AD + a], lg[a]);
        }
        float m = lg[0];
        #pragma unroll
        for (int a = 1; a < AD; a++) m = fmaxf(m, lg[a]);
        float se = 0.f;
        #pragma unroll
        for (int a = 0; a < AD; a++) se += __expf(lg[a] - m);
        float lse = __logf(se);
        float ent = 0.f;
        #pragma unroll
        for (int a = 0; a < AD; a++) {
            float lp = lg[a] - m - lse;
            ent -= __expf(lp) * lp;
        }
        int   act  = __ldg(&action[sr]);
        float logp = lg[act] - m - lse;

        if (s < Bn) {
            out[s]          = (float)act;
            out[Bn + s]     = logp;
            out[2 * Bn + s] = ent;
            out[3 * Bn + s] = valbuf[tid];
        }
    }
}

extern "C" void kernel_launch(void* const* d_in, const int* in_sizes, int n_in,
                              void* d_out, int out_size) {
    const float* x    = (const float*)d_in[0];
    const int*   act  = (const int*)  d_in[1];
    const float* W1   = (const float*)d_in[2];
    const float* b1   = (const float*)d_in[3];
    const float* W2   = (const float*)d_in[4];
    const float* b2   = (const float*)d_in[5];
    const float* Wh   = (const float*)d_in[6];
    const float* bh   = (const float*)d_in[7];
    const float* Wc1  = (const float*)d_in[8];
    const float* bc1  = (const float*)d_in[9];
    const float* Wc2  = (const float*)d_in[10];
    const float* bc2  = (const float*)d_in[11];
    const float* Wc3  = (const float*)d_in[12];
    const float* bc3  = (const float*)d_in[13];
    float* out = (float*)d_out;

    const int Bn = in_sizes[1];

    prep_b<<<(GTOT + 255) / 256, 256>>>(W1, Wc1, W2, Wc2);

    const int grid = (Bn + ROWS - 1) / ROWS;
    agent_mma<<<grid, BLOCK>>>(x, act, b1, b2, Wh, bh, bc1, bc2, Wc3, bc3, out, Bn);
}